// round 1
// baseline (speedup 1.0000x reference)
#include <cuda_runtime.h>
#include <math.h>

#define BDIM 4
#define NN   4096
#define DD   1536
#define HH   512
#define KA   8
#define MTOT (BDIM*NN)
#define R2   (400.0f*400.0f)

// ---------------- device scratch (static; no allocation) ----------------
__device__ float g_feat[(size_t)MTOT*HH];   // 32 MB
__device__ float g_agg [(size_t)MTOT*HH];   // 32 MB
__device__ float g_anorm[KA*DD];
__device__ float g_concept[BDIM*KA];
__device__ float g_latent[BDIM*HH];

// ---------------- zero accumulators (needed every graph replay) ----------
__global__ void zero_kernel() {
    int t = blockIdx.x * blockDim.x + threadIdx.x;
    if (t < BDIM*HH) g_latent[t] = 0.0f;
    if (t < BDIM*KA) g_concept[t] = 0.0f;
}

// ---------------- normalize anchors --------------------------------------
__global__ void anchor_norm_kernel(const float* __restrict__ anchors) {
    int k = blockIdx.x;
    int t = threadIdx.x;
    __shared__ float red[256];
    float s = 0.0f;
    for (int d = t; d < DD; d += 256) { float v = anchors[k*DD + d]; s += v*v; }
    red[t] = s; __syncthreads();
    for (int off = 128; off > 0; off >>= 1) {
        if (t < off) red[t] += red[t + off];
        __syncthreads();
    }
    float inv = 1.0f / fmaxf(sqrtf(red[0]), 1e-12f);
    for (int d = t; d < DD; d += 256) g_anorm[k*DD + d] = anchors[k*DD + d] * inv;
}

// ---------------- stream A: cosine scores vs anchors, mean over N --------
__global__ __launch_bounds__(256) void concept_kernel(const float* __restrict__ images) {
    int row = blockIdx.x;              // 0..MTOT-1
    int t   = threadIdx.x;
    const float* x = images + (size_t)row * DD;
    float dots[KA];
    #pragma unroll
    for (int k = 0; k < KA; k++) dots[k] = 0.0f;
    float ss = 0.0f;
    for (int d = t; d < DD; d += 256) {
        float v = x[d];
        ss += v * v;
        #pragma unroll
        for (int k = 0; k < KA; k++) dots[k] += v * g_anorm[k*DD + d];
    }
    // warp reduce 9 values
    #pragma unroll
    for (int off = 16; off > 0; off >>= 1) {
        ss += __shfl_down_sync(0xffffffffu, ss, off);
        #pragma unroll
        for (int k = 0; k < KA; k++) dots[k] += __shfl_down_sync(0xffffffffu, dots[k], off);
    }
    __shared__ float sred[8][KA + 1];
    int lane = t & 31, wid = t >> 5;
    if (lane == 0) {
        sred[wid][0] = ss;
        #pragma unroll
        for (int k = 0; k < KA; k++) sred[wid][k + 1] = dots[k];
    }
    __syncthreads();
    if (t == 0) {
        float S = 0.0f, Dk[KA];
        #pragma unroll
        for (int k = 0; k < KA; k++) Dk[k] = 0.0f;
        for (int w = 0; w < 8; w++) {
            S += sred[w][0];
            #pragma unroll
            for (int k = 0; k < KA; k++) Dk[k] += sred[w][k + 1];
        }
        float inv = 1.0f / fmaxf(sqrtf(S), 1e-12f);
        int b = row >> 12;
        #pragma unroll
        for (int k = 0; k < KA; k++)
            atomicAdd(&g_concept[b*KA + k], Dk[k] * inv * (1.0f / NN));
    }
}

// ---------------- feat = images @ W_feat + b_feat + pos @ W_pos ----------
// 128x128x8 register-tiled SGEMM, 256 threads, 8x8 per thread
__global__ __launch_bounds__(256) void feat_gemm_kernel(
    const float* __restrict__ A, const float* __restrict__ Wf,
    const float* __restrict__ bf, const float* __restrict__ Wp,
    const float* __restrict__ pos)
{
    __shared__ float As[8][132];
    __shared__ float Bs[8][128];
    int m0 = blockIdx.y * 128, n0 = blockIdx.x * 128;
    int tid = threadIdx.x;
    int tx = tid & 15, ty = tid >> 4;
    float acc[8][8] = {};

    int arow = tid >> 1;
    int ak   = (tid & 1) * 4;
    int brow = tid >> 5;
    int bcol = (tid & 31) * 4;

    for (int k0 = 0; k0 < DD; k0 += 8) {
        float4 a = *(const float4*)&A[(size_t)(m0 + arow) * DD + k0 + ak];
        As[ak + 0][arow] = a.x; As[ak + 1][arow] = a.y;
        As[ak + 2][arow] = a.z; As[ak + 3][arow] = a.w;
        *(float4*)&Bs[brow][bcol] = *(const float4*)&Wf[(size_t)(k0 + brow) * HH + n0 + bcol];
        __syncthreads();
        #pragma unroll
        for (int kk = 0; kk < 8; kk++) {
            float4 a0 = *(const float4*)&As[kk][ty * 8];
            float4 a1 = *(const float4*)&As[kk][ty * 8 + 4];
            float4 b0 = *(const float4*)&Bs[kk][tx * 8];
            float4 b1 = *(const float4*)&Bs[kk][tx * 8 + 4];
            float ar[8] = {a0.x,a0.y,a0.z,a0.w,a1.x,a1.y,a1.z,a1.w};
            float br[8] = {b0.x,b0.y,b0.z,b0.w,b1.x,b1.y,b1.z,b1.w};
            #pragma unroll
            for (int i = 0; i < 8; i++)
                #pragma unroll
                for (int j = 0; j < 8; j++) acc[i][j] += ar[i] * br[j];
        }
        __syncthreads();
    }

    #pragma unroll
    for (int i = 0; i < 8; i++) {
        int m = m0 + ty * 8 + i;
        float2 p = *(const float2*)&pos[(size_t)m * 2];
        #pragma unroll
        for (int j = 0; j < 8; j += 4) {
            int n = n0 + tx * 8 + j;
            float4 v;
            v.x = acc[i][j+0] + bf[n+0] + p.x * Wp[n+0] + p.y * Wp[HH + n+0];
            v.y = acc[i][j+1] + bf[n+1] + p.x * Wp[n+1] + p.y * Wp[HH + n+1];
            v.z = acc[i][j+2] + bf[n+2] + p.x * Wp[n+2] + p.y * Wp[HH + n+2];
            v.w = acc[i][j+3] + bf[n+3] + p.x * Wp[n+3] + p.y * Wp[HH + n+3];
            *(float4*)&g_feat[(size_t)m * HH + n] = v;
        }
    }
}

// ---------------- radius graph + mean aggregation (sparse gather) --------
// one block per node: compact neighbor list in smem, then gather relu(feat)
__global__ __launch_bounds__(256) void agg_kernel(const float* __restrict__ pos) {
    int gi = blockIdx.x;              // b*N + i
    int b  = gi >> 12;
    int i  = gi & (NN - 1);
    int t  = threadIdx.x;
    __shared__ int nlist[1024];
    __shared__ int ncnt;
    if (t == 0) ncnt = 0;
    __syncthreads();

    float2 pi = *(const float2*)&pos[(size_t)gi * 2];
    for (int j = t; j < NN; j += 256) {
        float2 pj = *(const float2*)&pos[(size_t)(b*NN + j) * 2];
        float dx = pi.x - pj.x, dy = pi.y - pj.y;
        float d2 = dx*dx + dy*dy;
        if (d2 < R2 && j != i) {
            int idx = atomicAdd(&ncnt, 1);
            if (idx < 1024) nlist[idx] = j;
        }
    }
    __syncthreads();
    int cnt = min(ncnt, 1024);

    float2 acc = make_float2(0.0f, 0.0f);
    const float2* fb = (const float2*)g_feat + (size_t)b * NN * (HH/2);
    for (int l = 0; l < cnt; l++) {
        int j = nlist[l];
        float2 v = fb[(size_t)j * (HH/2) + t];
        acc.x += fmaxf(v.x, 0.0f);
        acc.y += fmaxf(v.y, 0.0f);
    }
    float inv = 1.0f / fmaxf((float)cnt, 1.0f);
    float2 o = make_float2(acc.x * inv, acc.y * inv);
    ((float2*)g_agg)[(size_t)gi * (HH/2) + t] = o;
}

// ---------------- refined = relu(agg@W_gnn + feat@W_self); mean pool -----
__global__ __launch_bounds__(256) void refine_gemm_kernel(
    const float* __restrict__ Wgnn, const float* __restrict__ Wself)
{
    __shared__ float As[8][132];
    __shared__ float Bs[8][128];
    __shared__ float cred[16][128];
    int m0 = blockIdx.y * 128, n0 = blockIdx.x * 128;
    int tid = threadIdx.x;
    int tx = tid & 15, ty = tid >> 4;
    float acc[8][8] = {};

    int arow = tid >> 1;
    int ak   = (tid & 1) * 4;
    int brow = tid >> 5;
    int bcol = (tid & 31) * 4;

    for (int src = 0; src < 2; src++) {
        const float* A  = src ? g_feat : g_agg;
        const float* Bm = src ? Wself  : Wgnn;
        for (int k0 = 0; k0 < HH; k0 += 8) {
            float4 a = *(const float4*)&A[(size_t)(m0 + arow) * HH + k0 + ak];
            As[ak + 0][arow] = a.x; As[ak + 1][arow] = a.y;
            As[ak + 2][arow] = a.z; As[ak + 3][arow] = a.w;
            *(float4*)&Bs[brow][bcol] = *(const float4*)&Bm[(size_t)(k0 + brow) * HH + n0 + bcol];
            __syncthreads();
            #pragma unroll
            for (int kk = 0; kk < 8; kk++) {
                float4 a0 = *(const float4*)&As[kk][ty * 8];
                float4 a1 = *(const float4*)&As[kk][ty * 8 + 4];
                float4 b0 = *(const float4*)&Bs[kk][tx * 8];
                float4 b1 = *(const float4*)&Bs[kk][tx * 8 + 4];
                float ar[8] = {a0.x,a0.y,a0.z,a0.w,a1.x,a1.y,a1.z,a1.w};
                float br[8] = {b0.x,b0.y,b0.z,b0.w,b1.x,b1.y,b1.z,b1.w};
                #pragma unroll
                for (int i = 0; i < 8; i++)
                    #pragma unroll
                    for (int j = 0; j < 8; j++) acc[i][j] += ar[i] * br[j];
            }
            __syncthreads();
        }
    }

    // epilogue: relu + per-column partial sums over the 128 rows -> latent
    #pragma unroll
    for (int j = 0; j < 8; j++) {
        float s = 0.0f;
        #pragma unroll
        for (int i = 0; i < 8; i++) s += fmaxf(acc[i][j], 0.0f);
        cred[ty][tx * 8 + j] = s;
    }
    __syncthreads();
    if (tid < 128) {
        float s = 0.0f;
        #pragma unroll
        for (int w = 0; w < 16; w++) s += cred[w][tid];
        int b = m0 >> 12;   // 4096 % 128 == 0, block lies in one graph
        atomicAdd(&g_latent[b*HH + n0 + tid], s);
    }
}

// ---------------- finalize output ----------------------------------------
__global__ void finalize_kernel(float* __restrict__ out) {
    int t = blockIdx.x * blockDim.x + threadIdx.x;
    if (t >= BDIM * (HH + KA)) return;
    int b = t / (HH + KA), c = t % (HH + KA);
    out[t] = (c < HH) ? g_latent[b*HH + c] * (1.0f / NN)
                      : g_concept[b*KA + (c - HH)];
}

// ---------------- launch --------------------------------------------------
extern "C" void kernel_launch(void* const* d_in, const int* in_sizes, int n_in,
                              void* d_out, int out_size)
{
    const float* images    = (const float*)d_in[0];
    const float* positions = (const float*)d_in[1];
    const float* W_feat    = (const float*)d_in[2];
    const float* b_feat    = (const float*)d_in[3];
    const float* W_pos     = (const float*)d_in[4];
    const float* W_gnn     = (const float*)d_in[5];
    const float* W_self    = (const float*)d_in[6];
    const float* anchors   = (const float*)d_in[7];
    float* out = (float*)d_out;

    zero_kernel<<<8, 256>>>();
    anchor_norm_kernel<<<KA, 256>>>(anchors);
    concept_kernel<<<MTOT, 256>>>(images);

    dim3 gg(HH / 128, MTOT / 128);
    feat_gemm_kernel<<<gg, 256>>>(images, W_feat, b_feat, W_pos, positions);
    agg_kernel<<<MTOT, 256>>>(positions);
    refine_gemm_kernel<<<gg, 256>>>(W_gnn, W_self);
    finalize_kernel<<<(BDIM*(HH+KA) + 255) / 256, 256>>>(out);
}

// round 6
// speedup vs baseline: 1.8974x; 1.8974x over previous
#include <cuda_runtime.h>
#include <cuda_bf16.h>
#include <cstdint>
#include <math.h>

#define BDIM 4
#define NN   4096
#define DD   1536
#define HH   512
#define KA   8
#define MTOT (BDIM*NN)
#define R2   (400.0f*400.0f)

// ---------------- static device scratch ----------------------------------
__device__ __align__(16) __nv_bfloat16 g_img_hi[(size_t)MTOT*DD];
__device__ __align__(16) __nv_bfloat16 g_img_lo[(size_t)MTOT*DD];
__device__ __align__(16) __nv_bfloat16 g_feat_hi[(size_t)MTOT*HH];
__device__ __align__(16) __nv_bfloat16 g_feat_lo[(size_t)MTOT*HH];
__device__ __align__(16) __nv_bfloat16 g_agg_hi[(size_t)MTOT*HH];
__device__ __align__(16) __nv_bfloat16 g_agg_lo[(size_t)MTOT*HH];
__device__ __align__(16) __nv_bfloat16 g_Wf_hi[HH*DD];   // transposed [H][D]
__device__ __align__(16) __nv_bfloat16 g_Wf_lo[HH*DD];
__device__ __align__(16) __nv_bfloat16 g_Wg_hi[HH*HH];   // transposed [H][H]
__device__ __align__(16) __nv_bfloat16 g_Wg_lo[HH*HH];
__device__ __align__(16) __nv_bfloat16 g_Ws_hi[HH*HH];
__device__ __align__(16) __nv_bfloat16 g_Ws_lo[HH*HH];
__device__ float g_anorm[KA*DD];
__device__ float g_concept[BDIM*KA];
__device__ float g_latent[BDIM*HH];

// ---------------- PTX helpers (sm_80-class only) --------------------------
__device__ __forceinline__ uint32_t smem_u32(const void* p) {
    uint32_t a;
    asm("{ .reg .u64 t; cvta.to.shared.u64 t, %1; cvt.u32.u64 %0, t; }" : "=r"(a) : "l"(p));
    return a;
}
__device__ __forceinline__ void cp_async16(uint32_t dst, const void* src) {
    asm volatile("cp.async.cg.shared.global [%0], [%1], 16;\n"
                 :: "r"(dst), "l"(__cvta_generic_to_global(src)) : "memory");
}
__device__ __forceinline__ void ldsm4(uint32_t* r, uint32_t addr) {
    asm volatile("ldmatrix.sync.aligned.m8n8.x4.shared.b16 {%0,%1,%2,%3}, [%4];"
                 : "=r"(r[0]), "=r"(r[1]), "=r"(r[2]), "=r"(r[3]) : "r"(addr));
}
__device__ __forceinline__ void mma16816(float* d, const uint32_t* a, const uint32_t* b) {
    asm volatile("mma.sync.aligned.m16n8k16.row.col.f32.bf16.bf16.f32 "
                 "{%0,%1,%2,%3}, {%4,%5,%6,%7}, {%8,%9}, {%0,%1,%2,%3};"
                 : "+f"(d[0]), "+f"(d[1]), "+f"(d[2]), "+f"(d[3])
                 : "r"(a[0]), "r"(a[1]), "r"(a[2]), "r"(a[3]), "r"(b[0]), "r"(b[1]));
}
__device__ __forceinline__ uint32_t swz(uint32_t o) { return o ^ ((o >> 3) & 0x70); }
__device__ __forceinline__ void split_bf16(float v, __nv_bfloat16& h, __nv_bfloat16& l) {
    h = __float2bfloat16(v);
    l = __float2bfloat16(v - __bfloat162float(h));
}

// ---------------- utility kernels ----------------------------------------
__global__ void zero_kernel() {
    int t = blockIdx.x * blockDim.x + threadIdx.x;
    if (t < BDIM*HH) g_latent[t] = 0.0f;
    if (t < BDIM*KA) g_concept[t] = 0.0f;
}

__global__ void anchor_norm_kernel(const float* __restrict__ anchors) {
    int k = blockIdx.x, t = threadIdx.x;
    __shared__ float red[256];
    float s = 0.0f;
    for (int d = t; d < DD; d += 256) { float v = anchors[k*DD + d]; s += v*v; }
    red[t] = s; __syncthreads();
    for (int off = 128; off > 0; off >>= 1) { if (t < off) red[t] += red[t+off]; __syncthreads(); }
    float inv = 1.0f / fmaxf(sqrtf(red[0]), 1e-12f);
    for (int d = t; d < DD; d += 256) g_anorm[k*DD + d] = anchors[k*DD + d] * inv;
}

__global__ __launch_bounds__(256) void concept_kernel(const float* __restrict__ images) {
    int row = blockIdx.x, t = threadIdx.x;
    const float* x = images + (size_t)row * DD;
    float dots[KA];
    #pragma unroll
    for (int k = 0; k < KA; k++) dots[k] = 0.0f;
    float ss = 0.0f;
    for (int d = t; d < DD; d += 256) {
        float v = x[d];
        ss += v * v;
        #pragma unroll
        for (int k = 0; k < KA; k++) dots[k] += v * g_anorm[k*DD + d];
    }
    #pragma unroll
    for (int off = 16; off > 0; off >>= 1) {
        ss += __shfl_down_sync(0xffffffffu, ss, off);
        #pragma unroll
        for (int k = 0; k < KA; k++) dots[k] += __shfl_down_sync(0xffffffffu, dots[k], off);
    }
    __shared__ float sred[8][KA + 1];
    int lane = t & 31, wid = t >> 5;
    if (lane == 0) {
        sred[wid][0] = ss;
        #pragma unroll
        for (int k = 0; k < KA; k++) sred[wid][k+1] = dots[k];
    }
    __syncthreads();
    if (t == 0) {
        float S = 0.0f, Dk[KA];
        #pragma unroll
        for (int k = 0; k < KA; k++) Dk[k] = 0.0f;
        for (int w = 0; w < 8; w++) {
            S += sred[w][0];
            #pragma unroll
            for (int k = 0; k < KA; k++) Dk[k] += sred[w][k+1];
        }
        float inv = 1.0f / fmaxf(sqrtf(S), 1e-12f);
        int b = row >> 12;
        #pragma unroll
        for (int k = 0; k < KA; k++)
            atomicAdd(&g_concept[b*KA + k], Dk[k] * inv * (1.0f / NN));
    }
}

__global__ __launch_bounds__(256) void conv_img_kernel(const float* __restrict__ x) {
    size_t i = (size_t)blockIdx.x * 256 + threadIdx.x;   // unit of 4 floats
    float4 v = ((const float4*)x)[i];
    __nv_bfloat16 h0,l0,h1,l1,h2,l2,h3,l3;
    split_bf16(v.x,h0,l0); split_bf16(v.y,h1,l1); split_bf16(v.z,h2,l2); split_bf16(v.w,h3,l3);
    __nv_bfloat162 ph0; ph0.x=h0; ph0.y=h1;
    __nv_bfloat162 ph1; ph1.x=h2; ph1.y=h3;
    __nv_bfloat162 pl0; pl0.x=l0; pl0.y=l1;
    __nv_bfloat162 pl1; pl1.x=l2; pl1.y=l3;
    ((uint2*)g_img_hi)[i] = make_uint2(*(uint32_t*)&ph0, *(uint32_t*)&ph1);
    ((uint2*)g_img_lo)[i] = make_uint2(*(uint32_t*)&pl0, *(uint32_t*)&pl1);
}

__global__ __launch_bounds__(256) void conv_w_kernel(const float* __restrict__ W, int K, int which) {
    int idx = blockIdx.x * 256 + threadIdx.x;
    if (idx >= K * HH) return;
    int k = idx / HH, n = idx % HH;
    __nv_bfloat16 h, l;
    split_bf16(W[idx], h, l);
    size_t o = (size_t)n * K + k;
    if (which == 0)      { g_Wf_hi[o] = h; g_Wf_lo[o] = l; }
    else if (which == 1) { g_Wg_hi[o] = h; g_Wg_lo[o] = l; }
    else                 { g_Ws_hi[o] = h; g_Ws_lo[o] = l; }
}

// ---------------- HMMA GEMM ----------------------------------------------
// Block tile 128x128, BK=64 bf16, 8 warps (4x2), warp tile 32x64.
// 2-stage cp.async double buffer. A=[M,K] rowmajor bf16, B=[N,K] rowmajor bf16.
// MODE 0: feat = img@Wf (+bias+pos@Wp), split-store bf16 hi/lo
// MODE 1: refined = relu(agg@Wg + feat@Ws), column-pool into g_latent
#define STAGE_BYTES 32768
#define SB_OFF 16384
#define COLSUM_OFF 65536
#define GEMM_SMEM  (65536 + 640)

__device__ __forceinline__ void get_pass(int mode, int pass,
                                         const __nv_bfloat16*& A, const __nv_bfloat16*& B) {
    if (mode == 0) {
        A = (pass == 2) ? g_img_lo : g_img_hi;
        B = (pass == 1) ? g_Wf_lo  : g_Wf_hi;
    } else {
        switch (pass) {
            case 0:  A = g_agg_hi;  B = g_Wg_hi; break;
            case 1:  A = g_agg_hi;  B = g_Wg_lo; break;
            case 2:  A = g_agg_lo;  B = g_Wg_hi; break;
            case 3:  A = g_feat_hi; B = g_Ws_hi; break;
            case 4:  A = g_feat_hi; B = g_Ws_lo; break;
            default: A = g_feat_lo; B = g_Ws_hi; break;
        }
    }
}

template<int CPP, int LDA, int LDB, int MODE>
__device__ __forceinline__ void load_chunk(int tid, int m0, int n0, int i, int s, uint32_t sbase) {
    int pass = i / CPP;
    int k0 = (i - pass * CPP) * 64;
    const __nv_bfloat16 *A, *B;
    get_pass(MODE, pass, A, B);
    uint32_t sa = sbase + s * STAGE_BYTES;
    uint32_t sb = sa + SB_OFF;
    #pragma unroll
    for (int q = 0; q < 4; q++) {
        int e = q * 256 + tid;
        int row = e >> 3, kc = e & 7;
        cp_async16(sa + swz(row * 128 + kc * 16),
                   A + (size_t)(m0 + row) * LDA + k0 + kc * 8);
    }
    #pragma unroll
    for (int q = 0; q < 4; q++) {
        int e = q * 256 + tid;
        int row = e >> 3, kc = e & 7;
        cp_async16(sb + swz(row * 128 + kc * 16),
                   B + (size_t)(n0 + row) * LDB + k0 + kc * 8);
    }
    asm volatile("cp.async.commit_group;\n" ::: "memory");
}

template<int NPASS, int CPP, int LDA, int LDB, int MODE>
__global__ __launch_bounds__(256, 2) void gemm_kernel(
    const float* __restrict__ bias, const float* __restrict__ Wp,
    const float* __restrict__ pos)
{
    extern __shared__ char smem[];
    uint32_t sbase = smem_u32(smem);
    int tid = threadIdx.x;
    int wid = tid >> 5, lane = tid & 31;
    int m0 = blockIdx.x * 128;
    int n0 = blockIdx.y * 128;
    const int NITER = NPASS * CPP;

    int warp_m = (wid >> 1) * 32;
    int warp_n = (wid & 1) * 64;

    // per-lane ldmatrix row/half offsets
    int a_row  = warp_m + (lane & 15);
    int a_half = (lane >> 4) * 16;        // bytes
    int b_row  = warp_n + (lane & 7) + ((lane >> 4) * 8);
    int b_half = ((lane >> 3) & 1) * 16;  // bytes

    float acc[2][8][4];
    #pragma unroll
    for (int mt = 0; mt < 2; mt++)
        #pragma unroll
        for (int nt = 0; nt < 8; nt++)
            #pragma unroll
            for (int j = 0; j < 4; j++) acc[mt][nt][j] = 0.0f;

    if (MODE == 1) {
        for (int c = tid; c < 128; c += 256) *(float*)(smem + COLSUM_OFF + 4*c) = 0.0f;
    }
    __syncthreads();

    load_chunk<CPP,LDA,LDB,MODE>(tid, m0, n0, 0, 0, sbase);
    load_chunk<CPP,LDA,LDB,MODE>(tid, m0, n0, 1, 1, sbase);

    for (int i = 0; i < NITER; i++) {
        int s = i & 1;
        if (i + 1 < NITER) asm volatile("cp.async.wait_group 1;\n" ::: "memory");
        else               asm volatile("cp.async.wait_group 0;\n" ::: "memory");
        __syncthreads();
        uint32_t sa = sbase + s * STAGE_BYTES;
        uint32_t sb = sa + SB_OFF;
        #pragma unroll
        for (int ks = 0; ks < 4; ks++) {
            uint32_t afr[2][4], bfr[4][4];
            #pragma unroll
            for (int mt = 0; mt < 2; mt++)
                ldsm4(afr[mt], sa + swz((a_row + mt*16) * 128 + ks*32 + a_half));
            #pragma unroll
            for (int g = 0; g < 4; g++)
                ldsm4(bfr[g], sb + swz((b_row + g*16) * 128 + ks*32 + b_half));
            #pragma unroll
            for (int mt = 0; mt < 2; mt++)
                #pragma unroll
                for (int g = 0; g < 4; g++) {
                    mma16816(acc[mt][2*g+0], afr[mt], &bfr[g][0]);
                    mma16816(acc[mt][2*g+1], afr[mt], &bfr[g][2]);
                }
        }
        __syncthreads();
        if (i + 2 < NITER)
            load_chunk<CPP,LDA,LDB,MODE>(tid, m0, n0, i + 2, s, sbase);
    }

    int r0 = lane >> 2;        // 0..7
    int cp = (lane & 3) * 2;   // 0,2,4,6

    if (MODE == 0) {
        // columns this thread touches: n0 + warp_n + nt*8 + cp (+1)
        float cb[16], cwx[16], cwy[16];
        #pragma unroll
        for (int nt = 0; nt < 8; nt++) {
            int n = n0 + warp_n + nt*8 + cp;
            cb[2*nt]   = bias[n];   cb[2*nt+1]   = bias[n+1];
            cwx[2*nt]  = Wp[n];     cwx[2*nt+1]  = Wp[n+1];
            cwy[2*nt]  = Wp[HH+n];  cwy[2*nt+1]  = Wp[HH+n+1];
        }
        #pragma unroll
        for (int mt = 0; mt < 2; mt++) {
            #pragma unroll
            for (int half = 0; half < 2; half++) {
                int m = m0 + warp_m + mt*16 + r0 + half*8;
                float2 p = *(const float2*)&pos[(size_t)m * 2];
                #pragma unroll
                for (int nt = 0; nt < 8; nt++) {
                    int n = n0 + warp_n + nt*8 + cp;
                    float v0 = acc[mt][nt][2*half+0] + cb[2*nt]   + p.x*cwx[2*nt]   + p.y*cwy[2*nt];
                    float v1 = acc[mt][nt][2*half+1] + cb[2*nt+1] + p.x*cwx[2*nt+1] + p.y*cwy[2*nt+1];
                    __nv_bfloat16 h0,l0,h1,l1;
                    split_bf16(v0,h0,l0); split_bf16(v1,h1,l1);
                    __nv_bfloat162 hp; hp.x=h0; hp.y=h1;
                    __nv_bfloat162 lp; lp.x=l0; lp.y=l1;
                    *(uint32_t*)&g_feat_hi[(size_t)m * HH + n] = *(uint32_t*)&hp;
                    *(uint32_t*)&g_feat_lo[(size_t)m * HH + n] = *(uint32_t*)&lp;
                }
            }
        }
    } else {
        float* colsum = (float*)(smem + COLSUM_OFF);
        #pragma unroll
        for (int nt = 0; nt < 8; nt++) {
            float s0 = 0.0f, s1 = 0.0f;
            #pragma unroll
            for (int mt = 0; mt < 2; mt++) {
                s0 += fmaxf(acc[mt][nt][0], 0.0f) + fmaxf(acc[mt][nt][2], 0.0f);
                s1 += fmaxf(acc[mt][nt][1], 0.0f) + fmaxf(acc[mt][nt][3], 0.0f);
            }
            // reduce over r0 (lane bits 2,3,4)
            #pragma unroll
            for (int off = 4; off <= 16; off <<= 1) {
                s0 += __shfl_xor_sync(0xffffffffu, s0, off);
                s1 += __shfl_xor_sync(0xffffffffu, s1, off);
            }
            if (lane < 4) {
                int c = warp_n + nt*8 + lane*2;
                atomicAdd(&colsum[c], s0);
                atomicAdd(&colsum[c+1], s1);
            }
        }
        __syncthreads();
        int b = m0 >> 12;
        if (tid < 128) atomicAdd(&g_latent[b * HH + n0 + tid], colsum[tid]);
    }
}

// ---------------- radius graph + mean aggregation -------------------------
#define NPB 4
__global__ __launch_bounds__(256) void agg_kernel(const float* __restrict__ pos) {
    int base = blockIdx.x * NPB;
    int b = base >> 12;
    int t = threadIdx.x;
    __shared__ int nlist[NPB][512];
    __shared__ int ncnt[NPB];
    if (t < NPB) ncnt[t] = 0;
    __syncthreads();

    float2 pi[NPB];
    #pragma unroll
    for (int u = 0; u < NPB; u++) pi[u] = *(const float2*)&pos[(size_t)(base + u) * 2];

    for (int j = t; j < NN; j += 256) {
        float2 pj = *(const float2*)&pos[(size_t)(b * NN + j) * 2];
        #pragma unroll
        for (int u = 0; u < NPB; u++) {
            float dx = pi[u].x - pj.x, dy = pi[u].y - pj.y;
            float d2 = dx*dx + dy*dy;
            if (d2 < R2 && (b * NN + j) != (base + u)) {
                int idx = atomicAdd(&ncnt[u], 1);
                if (idx < 512) nlist[u][idx] = j;
            }
        }
    }
    __syncthreads();

    const uint32_t* fh = (const uint32_t*)g_feat_hi + (size_t)b * NN * (HH/2);
    const uint32_t* fl = (const uint32_t*)g_feat_lo + (size_t)b * NN * (HH/2);
    #pragma unroll 1
    for (int u = 0; u < NPB; u++) {
        int cnt = min(ncnt[u], 512);
        float2 acc = make_float2(0.0f, 0.0f);
        for (int l = 0; l < cnt; l++) {
            int j = nlist[u][l];
            uint32_t hv = fh[(size_t)j * (HH/2) + t];
            uint32_t lv = fl[(size_t)j * (HH/2) + t];
            __nv_bfloat162 hb = *(__nv_bfloat162*)&hv;
            __nv_bfloat162 lb = *(__nv_bfloat162*)&lv;
            acc.x += fmaxf(__bfloat162float(hb.x) + __bfloat162float(lb.x), 0.0f);
            acc.y += fmaxf(__bfloat162float(hb.y) + __bfloat162float(lb.y), 0.0f);
        }
        float inv = 1.0f / fmaxf((float)cnt, 1.0f);
        __nv_bfloat16 h0,l0,h1,l1;
        split_bf16(acc.x * inv, h0, l0);
        split_bf16(acc.y * inv, h1, l1);
        __nv_bfloat162 hp; hp.x=h0; hp.y=h1;
        __nv_bfloat162 lp; lp.x=l0; lp.y=l1;
        ((uint32_t*)g_agg_hi)[(size_t)(base + u) * (HH/2) + t] = *(uint32_t*)&hp;
        ((uint32_t*)g_agg_lo)[(size_t)(base + u) * (HH/2) + t] = *(uint32_t*)&lp;
    }
}

// ---------------- finalize ------------------------------------------------
__global__ void finalize_kernel(float* __restrict__ out) {
    int t = blockIdx.x * blockDim.x + threadIdx.x;
    if (t >= BDIM * (HH + KA)) return;
    int b = t / (HH + KA), c = t % (HH + KA);
    out[t] = (c < HH) ? g_latent[b*HH + c] * (1.0f / NN)
                      : g_concept[b*KA + (c - HH)];
}

// ---------------- launch --------------------------------------------------
extern "C" void kernel_launch(void* const* d_in, const int* in_sizes, int n_in,
                              void* d_out, int out_size)
{
    const float* images    = (const float*)d_in[0];
    const float* positions = (const float*)d_in[1];
    const float* W_feat    = (const float*)d_in[2];
    const float* b_feat    = (const float*)d_in[3];
    const float* W_pos     = (const float*)d_in[4];
    const float* W_gnn     = (const float*)d_in[5];
    const float* W_self    = (const float*)d_in[6];
    const float* anchors   = (const float*)d_in[7];
    float* out = (float*)d_out;

    cudaFuncSetAttribute(gemm_kernel<3, 24, DD, DD, 0>,
                         cudaFuncAttributeMaxDynamicSharedMemorySize, GEMM_SMEM);
    cudaFuncSetAttribute(gemm_kernel<6, 8, HH, HH, 1>,
                         cudaFuncAttributeMaxDynamicSharedMemorySize, GEMM_SMEM);

    zero_kernel<<<8, 256>>>();
    anchor_norm_kernel<<<KA, 256>>>(anchors);
    conv_img_kernel<<<(MTOT*(DD/4))/256, 256>>>(images);
    conv_w_kernel<<<(DD*HH + 255)/256, 256>>>(W_feat, DD, 0);
    conv_w_kernel<<<(HH*HH + 255)/256, 256>>>(W_gnn, HH, 1);
    conv_w_kernel<<<(HH*HH + 255)/256, 256>>>(W_self, HH, 2);
    concept_kernel<<<MTOT, 256>>>(images);

    dim3 gg(MTOT/128, HH/128);
    gemm_kernel<3, 24, DD, DD, 0><<<gg, 256, GEMM_SMEM>>>(b_feat, W_pos, positions);
    agg_kernel<<<MTOT/NPB, 256>>>(positions);
    gemm_kernel<6, 8, HH, HH, 1><<<gg, 256, GEMM_SMEM>>>(nullptr, nullptr, nullptr);
    finalize_kernel<<<(BDIM*(HH+KA) + 255)/256, 256>>>(out);
}

// round 7
// speedup vs baseline: 2.0400x; 1.0751x over previous
#include <cuda_runtime.h>
#include <cuda_bf16.h>
#include <cstdint>
#include <math.h>

#define BDIM 4
#define NN   4096
#define DD   1536
#define HH   512
#define KA   8
#define MTOT (BDIM*NN)
#define R2   (400.0f*400.0f)

// ---------------- static device scratch ----------------------------------
__device__ __align__(16) __nv_bfloat16 g_img_hi[(size_t)MTOT*DD];
__device__ __align__(16) __nv_bfloat16 g_img_lo[(size_t)MTOT*DD];
__device__ __align__(16) __nv_bfloat16 g_feat_hi[(size_t)MTOT*HH];
__device__ __align__(16) __nv_bfloat16 g_feat_lo[(size_t)MTOT*HH];
__device__ __align__(16) __nv_bfloat16 g_agg_hi[(size_t)MTOT*HH];
__device__ __align__(16) __nv_bfloat16 g_agg_lo[(size_t)MTOT*HH];
__device__ __align__(16) __nv_bfloat16 g_Wf_hi[HH*DD];   // transposed [H][D]
__device__ __align__(16) __nv_bfloat16 g_Wf_lo[HH*DD];
__device__ __align__(16) __nv_bfloat16 g_Wg_hi[HH*HH];   // transposed [H][H]
__device__ __align__(16) __nv_bfloat16 g_Wg_lo[HH*HH];
__device__ __align__(16) __nv_bfloat16 g_Ws_hi[HH*HH];
__device__ __align__(16) __nv_bfloat16 g_Ws_lo[HH*HH];
__device__ __align__(16) float g_anorm_t[DD*KA];   // transposed [D][K]
__device__ float g_concept[BDIM*KA];
__device__ float g_latent[BDIM*HH];

// ---------------- PTX helpers (sm_80-class only) --------------------------
__device__ __forceinline__ uint32_t smem_u32(const void* p) {
    uint32_t a;
    asm("{ .reg .u64 t; cvta.to.shared.u64 t, %1; cvt.u32.u64 %0, t; }" : "=r"(a) : "l"(p));
    return a;
}
__device__ __forceinline__ void cp_async16(uint32_t dst, const void* src) {
    asm volatile("cp.async.cg.shared.global [%0], [%1], 16;\n"
                 :: "r"(dst), "l"(__cvta_generic_to_global(src)) : "memory");
}
__device__ __forceinline__ void ldsm4(uint32_t* r, uint32_t addr) {
    asm volatile("ldmatrix.sync.aligned.m8n8.x4.shared.b16 {%0,%1,%2,%3}, [%4];"
                 : "=r"(r[0]), "=r"(r[1]), "=r"(r[2]), "=r"(r[3]) : "r"(addr));
}
__device__ __forceinline__ void mma16816(float* d, const uint32_t* a, const uint32_t* b) {
    asm volatile("mma.sync.aligned.m16n8k16.row.col.f32.bf16.bf16.f32 "
                 "{%0,%1,%2,%3}, {%4,%5,%6,%7}, {%8,%9}, {%0,%1,%2,%3};"
                 : "+f"(d[0]), "+f"(d[1]), "+f"(d[2]), "+f"(d[3])
                 : "r"(a[0]), "r"(a[1]), "r"(a[2]), "r"(a[3]), "r"(b[0]), "r"(b[1]));
}
__device__ __forceinline__ uint32_t swz(uint32_t o) { return o ^ ((o >> 3) & 0x70); }
__device__ __forceinline__ void split_bf16(float v, __nv_bfloat16& h, __nv_bfloat16& l) {
    h = __float2bfloat16(v);
    l = __float2bfloat16(v - __bfloat162float(h));
}

// ---------------- utility kernels ----------------------------------------
__global__ void zero_kernel() {
    int t = blockIdx.x * blockDim.x + threadIdx.x;
    if (t < BDIM*HH) g_latent[t] = 0.0f;
    if (t < BDIM*KA) g_concept[t] = 0.0f;
}

__global__ void anchor_norm_kernel(const float* __restrict__ anchors) {
    int k = blockIdx.x, t = threadIdx.x;
    __shared__ float red[256];
    float s = 0.0f;
    for (int d = t; d < DD; d += 256) { float v = anchors[k*DD + d]; s += v*v; }
    red[t] = s; __syncthreads();
    for (int off = 128; off > 0; off >>= 1) { if (t < off) red[t] += red[t+off]; __syncthreads(); }
    float inv = 1.0f / fmaxf(sqrtf(red[0]), 1e-12f);
    for (int d = t; d < DD; d += 256) g_anorm_t[(size_t)d*KA + k] = anchors[k*DD + d] * inv;
}

// ---- fused: images -> bf16 hi/lo + cosine concept scores -----------------
__global__ __launch_bounds__(192) void conv_img_concept(const float* __restrict__ images) {
    int row = blockIdx.x, t = threadIdx.x;
    const float4* x4 = (const float4*)(images + (size_t)row * DD);
    const float4* an4 = (const float4*)g_anorm_t;   // [D][8] -> 2 float4 per d
    float ss = 0.0f;
    float dots[KA];
    #pragma unroll
    for (int k = 0; k < KA; k++) dots[k] = 0.0f;

    #pragma unroll
    for (int half = 0; half < 2; half++) {
        int idx = t + half * 192;       // float4 index within row (0..383)
        float4 v = x4[idx];
        float vv[4] = {v.x, v.y, v.z, v.w};
        __nv_bfloat16 h[4], l[4];
        #pragma unroll
        for (int e = 0; e < 4; e++) {
            float val = vv[e];
            ss += val * val;
            split_bf16(val, h[e], l[e]);
            int d = idx * 4 + e;
            float4 a0 = an4[d*2], a1 = an4[d*2 + 1];
            dots[0] += val*a0.x; dots[1] += val*a0.y; dots[2] += val*a0.z; dots[3] += val*a0.w;
            dots[4] += val*a1.x; dots[5] += val*a1.y; dots[6] += val*a1.z; dots[7] += val*a1.w;
        }
        __nv_bfloat162 hp0; hp0.x=h[0]; hp0.y=h[1];
        __nv_bfloat162 hp1; hp1.x=h[2]; hp1.y=h[3];
        __nv_bfloat162 lp0; lp0.x=l[0]; lp0.y=l[1];
        __nv_bfloat162 lp1; lp1.x=l[2]; lp1.y=l[3];
        ((uint2*)g_img_hi)[(size_t)row * 384 + idx] = make_uint2(*(uint32_t*)&hp0, *(uint32_t*)&hp1);
        ((uint2*)g_img_lo)[(size_t)row * 384 + idx] = make_uint2(*(uint32_t*)&lp0, *(uint32_t*)&lp1);
    }

    // reduce ss + dots over 192 threads (6 warps)
    #pragma unroll
    for (int off = 16; off > 0; off >>= 1) {
        ss += __shfl_down_sync(0xffffffffu, ss, off);
        #pragma unroll
        for (int k = 0; k < KA; k++) dots[k] += __shfl_down_sync(0xffffffffu, dots[k], off);
    }
    __shared__ float sred[6][KA + 1];
    int lane = t & 31, wid = t >> 5;
    if (lane == 0) {
        sred[wid][0] = ss;
        #pragma unroll
        for (int k = 0; k < KA; k++) sred[wid][k+1] = dots[k];
    }
    __syncthreads();
    if (t == 0) {
        float S = 0.0f, Dk[KA];
        #pragma unroll
        for (int k = 0; k < KA; k++) Dk[k] = 0.0f;
        #pragma unroll
        for (int w = 0; w < 6; w++) {
            S += sred[w][0];
            #pragma unroll
            for (int k = 0; k < KA; k++) Dk[k] += sred[w][k+1];
        }
        float inv = 1.0f / fmaxf(sqrtf(S), 1e-12f);
        int b = row >> 12;
        #pragma unroll
        for (int k = 0; k < KA; k++)
            atomicAdd(&g_concept[b*KA + k], Dk[k] * inv * (1.0f / NN));
    }
}

// ---- weight transpose via smem tile (coalesced both ways) ---------------
__global__ __launch_bounds__(256) void conv_w_kernel(const float* __restrict__ W, int K, int which) {
    __shared__ float tile[32][33];
    int k0 = blockIdx.x * 32, n0 = blockIdx.y * 32;
    int tx = threadIdx.x & 31, ty = threadIdx.x >> 5;   // 8 rows of 32
    #pragma unroll
    for (int r = 0; r < 32; r += 8)
        tile[ty + r][tx] = W[(size_t)(k0 + ty + r) * HH + n0 + tx];
    __syncthreads();
    #pragma unroll
    for (int r = 0; r < 32; r += 8) {
        int n = n0 + ty + r, k = k0 + tx;
        __nv_bfloat16 h, l;
        split_bf16(tile[tx][ty + r], h, l);
        size_t o = (size_t)n * K + k;
        if (which == 0)      { g_Wf_hi[o] = h; g_Wf_lo[o] = l; }
        else if (which == 1) { g_Wg_hi[o] = h; g_Wg_lo[o] = l; }
        else                 { g_Ws_hi[o] = h; g_Ws_lo[o] = l; }
    }
}

// ---------------- HMMA GEMM with shared-A pass fusion ---------------------
// Block tile 128x128, BK=64, 8 warps, warp tile 32x64, 2-stage cp.async.
// Each chunk loads one A tile and 1-2 B tiles (hi/lo of same weight).
// MODE 0: feat = img@Wf (+bias+pos@Wp) -> bf16 hi/lo   (48 chunks)
// MODE 1: relu(agg@Wg + feat@Ws) -> column-pool g_latent (32 chunks)
#define STAGE_BYTES 49152
#define SB0_OFF 16384
#define SB1_OFF 32768
#define COLSUM_OFF 98304
#define GEMM_SMEM  (98304 + 512)

struct Chunk { const __nv_bfloat16 *A, *B0, *B1; int k0; int nb; };

template<int MODE>
__device__ __forceinline__ void get_chunk(int i, Chunk& c) {
    if (MODE == 0) {
        if (i < 24) { c.A = g_img_hi; c.k0 = i*64;      c.B0 = g_Wf_hi; c.B1 = g_Wf_lo; c.nb = 2; }
        else        { c.A = g_img_lo; c.k0 = (i-24)*64; c.B0 = g_Wf_hi; c.B1 = g_Wf_hi; c.nb = 1; }
    } else {
        int seg = i >> 3;
        c.k0 = (i & 7) * 64;
        switch (seg) {
            case 0:  c.A = g_agg_hi;  c.B0 = g_Wg_hi; c.B1 = g_Wg_lo; c.nb = 2; break;
            case 1:  c.A = g_agg_lo;  c.B0 = g_Wg_hi; c.B1 = g_Wg_hi; c.nb = 1; break;
            case 2:  c.A = g_feat_hi; c.B0 = g_Ws_hi; c.B1 = g_Ws_lo; c.nb = 2; break;
            default: c.A = g_feat_lo; c.B0 = g_Ws_hi; c.B1 = g_Ws_hi; c.nb = 1; break;
        }
    }
}

template<int LDA, int LDB, int MODE>
__device__ __forceinline__ void load_chunk(int tid, int m0, int n0, int i, int s, uint32_t sbase) {
    Chunk c; get_chunk<MODE>(i, c);
    uint32_t sa = sbase + s * STAGE_BYTES;
    #pragma unroll
    for (int q = 0; q < 4; q++) {
        int e = q * 256 + tid;
        int row = e >> 3, kc = e & 7;
        cp_async16(sa + swz(row * 128 + kc * 16),
                   c.A + (size_t)(m0 + row) * LDA + c.k0 + kc * 8);
    }
    #pragma unroll
    for (int q = 0; q < 4; q++) {
        int e = q * 256 + tid;
        int row = e >> 3, kc = e & 7;
        cp_async16(sa + SB0_OFF + swz(row * 128 + kc * 16),
                   c.B0 + (size_t)(n0 + row) * LDB + c.k0 + kc * 8);
    }
    if (c.nb == 2) {
        #pragma unroll
        for (int q = 0; q < 4; q++) {
            int e = q * 256 + tid;
            int row = e >> 3, kc = e & 7;
            cp_async16(sa + SB1_OFF + swz(row * 128 + kc * 16),
                       c.B1 + (size_t)(n0 + row) * LDB + c.k0 + kc * 8);
        }
    }
    asm volatile("cp.async.commit_group;\n" ::: "memory");
}

template<int NCHUNK, int LDA, int LDB, int MODE>
__global__ __launch_bounds__(256, 2) void gemm_kernel(
    const float* __restrict__ bias, const float* __restrict__ Wp,
    const float* __restrict__ pos)
{
    extern __shared__ char smem[];
    uint32_t sbase = smem_u32(smem);
    int tid = threadIdx.x;
    int wid = tid >> 5, lane = tid & 31;
    int m0 = blockIdx.x * 128;
    int n0 = blockIdx.y * 128;

    int warp_m = (wid >> 1) * 32;
    int warp_n = (wid & 1) * 64;

    int a_row  = warp_m + (lane & 15);
    int a_half = (lane >> 4) * 16;
    int b_row  = warp_n + (lane & 7) + ((lane >> 4) * 8);
    int b_half = ((lane >> 3) & 1) * 16;

    float acc[2][8][4];
    #pragma unroll
    for (int mt = 0; mt < 2; mt++)
        #pragma unroll
        for (int nt = 0; nt < 8; nt++)
            #pragma unroll
            for (int j = 0; j < 4; j++) acc[mt][nt][j] = 0.0f;

    if (MODE == 1) {
        for (int c = tid; c < 128; c += 256) *(float*)(smem + COLSUM_OFF + 4*c) = 0.0f;
    }
    __syncthreads();

    load_chunk<LDA,LDB,MODE>(tid, m0, n0, 0, 0, sbase);
    load_chunk<LDA,LDB,MODE>(tid, m0, n0, 1, 1, sbase);

    for (int i = 0; i < NCHUNK; i++) {
        int s = i & 1;
        Chunk c; get_chunk<MODE>(i, c);
        if (i + 1 < NCHUNK) asm volatile("cp.async.wait_group 1;\n" ::: "memory");
        else                asm volatile("cp.async.wait_group 0;\n" ::: "memory");
        __syncthreads();
        uint32_t sa = sbase + s * STAGE_BYTES;
        bool two = (c.nb == 2);
        #pragma unroll
        for (int ks = 0; ks < 4; ks++) {
            uint32_t afr[2][4];
            #pragma unroll
            for (int mt = 0; mt < 2; mt++)
                ldsm4(afr[mt], sa + swz((a_row + mt*16) * 128 + ks*32 + a_half));
            {
                uint32_t bfr[4][4];
                #pragma unroll
                for (int g = 0; g < 4; g++)
                    ldsm4(bfr[g], sa + SB0_OFF + swz((b_row + g*16) * 128 + ks*32 + b_half));
                #pragma unroll
                for (int mt = 0; mt < 2; mt++)
                    #pragma unroll
                    for (int g = 0; g < 4; g++) {
                        mma16816(acc[mt][2*g+0], afr[mt], &bfr[g][0]);
                        mma16816(acc[mt][2*g+1], afr[mt], &bfr[g][2]);
                    }
            }
            if (two) {
                uint32_t bfr[4][4];
                #pragma unroll
                for (int g = 0; g < 4; g++)
                    ldsm4(bfr[g], sa + SB1_OFF + swz((b_row + g*16) * 128 + ks*32 + b_half));
                #pragma unroll
                for (int mt = 0; mt < 2; mt++)
                    #pragma unroll
                    for (int g = 0; g < 4; g++) {
                        mma16816(acc[mt][2*g+0], afr[mt], &bfr[g][0]);
                        mma16816(acc[mt][2*g+1], afr[mt], &bfr[g][2]);
                    }
            }
        }
        __syncthreads();
        if (i + 2 < NCHUNK)
            load_chunk<LDA,LDB,MODE>(tid, m0, n0, i + 2, s, sbase);
    }

    int r0 = lane >> 2;
    int cp = (lane & 3) * 2;

    if (MODE == 0) {
        float cb[16], cwx[16], cwy[16];
        #pragma unroll
        for (int nt = 0; nt < 8; nt++) {
            int n = n0 + warp_n + nt*8 + cp;
            cb[2*nt]   = bias[n];   cb[2*nt+1]   = bias[n+1];
            cwx[2*nt]  = Wp[n];     cwx[2*nt+1]  = Wp[n+1];
            cwy[2*nt]  = Wp[HH+n];  cwy[2*nt+1]  = Wp[HH+n+1];
        }
        #pragma unroll
        for (int mt = 0; mt < 2; mt++) {
            #pragma unroll
            for (int half = 0; half < 2; half++) {
                int m = m0 + warp_m + mt*16 + r0 + half*8;
                float2 p = *(const float2*)&pos[(size_t)m * 2];
                #pragma unroll
                for (int nt = 0; nt < 8; nt++) {
                    int n = n0 + warp_n + nt*8 + cp;
                    float v0 = acc[mt][nt][2*half+0] + cb[2*nt]   + p.x*cwx[2*nt]   + p.y*cwy[2*nt];
                    float v1 = acc[mt][nt][2*half+1] + cb[2*nt+1] + p.x*cwx[2*nt+1] + p.y*cwy[2*nt+1];
                    __nv_bfloat16 h0,l0,h1,l1;
                    split_bf16(v0,h0,l0); split_bf16(v1,h1,l1);
                    __nv_bfloat162 hp; hp.x=h0; hp.y=h1;
                    __nv_bfloat162 lp; lp.x=l0; lp.y=l1;
                    *(uint32_t*)&g_feat_hi[(size_t)m * HH + n] = *(uint32_t*)&hp;
                    *(uint32_t*)&g_feat_lo[(size_t)m * HH + n] = *(uint32_t*)&lp;
                }
            }
        }
    } else {
        float* colsum = (float*)(smem + COLSUM_OFF);
        #pragma unroll
        for (int nt = 0; nt < 8; nt++) {
            float s0 = 0.0f, s1 = 0.0f;
            #pragma unroll
            for (int mt = 0; mt < 2; mt++) {
                s0 += fmaxf(acc[mt][nt][0], 0.0f) + fmaxf(acc[mt][nt][2], 0.0f);
                s1 += fmaxf(acc[mt][nt][1], 0.0f) + fmaxf(acc[mt][nt][3], 0.0f);
            }
            #pragma unroll
            for (int off = 4; off <= 16; off <<= 1) {
                s0 += __shfl_xor_sync(0xffffffffu, s0, off);
                s1 += __shfl_xor_sync(0xffffffffu, s1, off);
            }
            if (lane < 4) {
                int c = warp_n + nt*8 + lane*2;
                atomicAdd(&colsum[c], s0);
                atomicAdd(&colsum[c+1], s1);
            }
        }
        __syncthreads();
        int b = m0 >> 12;
        if (tid < 128) atomicAdd(&g_latent[b * HH + n0 + tid], colsum[tid]);
    }
}

// ---------------- radius graph + mean aggregation -------------------------
#define NPB 8
__global__ __launch_bounds__(256) void agg_kernel(const float* __restrict__ pos) {
    int base = blockIdx.x * NPB;
    int b = base >> 12;
    int t = threadIdx.x;
    __shared__ int nlist[NPB][512];
    __shared__ int ncnt[NPB];
    if (t < NPB) ncnt[t] = 0;
    __syncthreads();

    float2 pi[NPB];
    #pragma unroll
    for (int u = 0; u < NPB; u++) pi[u] = *(const float2*)&pos[(size_t)(base + u) * 2];

    for (int j = t; j < NN; j += 256) {
        float2 pj = *(const float2*)&pos[(size_t)(b * NN + j) * 2];
        #pragma unroll
        for (int u = 0; u < NPB; u++) {
            float dx = pi[u].x - pj.x, dy = pi[u].y - pj.y;
            float d2 = dx*dx + dy*dy;
            if (d2 < R2 && (b * NN + j) != (base + u)) {
                int idx = atomicAdd(&ncnt[u], 1);
                if (idx < 512) nlist[u][idx] = j;
            }
        }
    }
    __syncthreads();

    const uint32_t* fh = (const uint32_t*)g_feat_hi + (size_t)b * NN * (HH/2);
    const uint32_t* fl = (const uint32_t*)g_feat_lo + (size_t)b * NN * (HH/2);
    #pragma unroll 1
    for (int u = 0; u < NPB; u++) {
        int cnt = min(ncnt[u], 512);
        float2 acc = make_float2(0.0f, 0.0f);
        for (int l = 0; l < cnt; l++) {
            int j = nlist[u][l];
            uint32_t hv = fh[(size_t)j * (HH/2) + t];
            uint32_t lv = fl[(size_t)j * (HH/2) + t];
            __nv_bfloat162 hb = *(__nv_bfloat162*)&hv;
            __nv_bfloat162 lb = *(__nv_bfloat162*)&lv;
            acc.x += fmaxf(__bfloat162float(hb.x) + __bfloat162float(lb.x), 0.0f);
            acc.y += fmaxf(__bfloat162float(hb.y) + __bfloat162float(lb.y), 0.0f);
        }
        float inv = 1.0f / fmaxf((float)cnt, 1.0f);
        __nv_bfloat16 h0,l0,h1,l1;
        split_bf16(acc.x * inv, h0, l0);
        split_bf16(acc.y * inv, h1, l1);
        __nv_bfloat162 hp; hp.x=h0; hp.y=h1;
        __nv_bfloat162 lp; lp.x=l0; lp.y=l1;
        ((uint32_t*)g_agg_hi)[(size_t)(base + u) * (HH/2) + t] = *(uint32_t*)&hp;
        ((uint32_t*)g_agg_lo)[(size_t)(base + u) * (HH/2) + t] = *(uint32_t*)&lp;
    }
}

// ---------------- finalize ------------------------------------------------
__global__ void finalize_kernel(float* __restrict__ out) {
    int t = blockIdx.x * blockDim.x + threadIdx.x;
    if (t >= BDIM * (HH + KA)) return;
    int b = t / (HH + KA), c = t % (HH + KA);
    out[t] = (c < HH) ? g_latent[b*HH + c] * (1.0f / NN)
                      : g_concept[b*KA + (c - HH)];
}

// ---------------- launch --------------------------------------------------
extern "C" void kernel_launch(void* const* d_in, const int* in_sizes, int n_in,
                              void* d_out, int out_size)
{
    const float* images    = (const float*)d_in[0];
    const float* positions = (const float*)d_in[1];
    const float* W_feat    = (const float*)d_in[2];
    const float* b_feat    = (const float*)d_in[3];
    const float* W_pos     = (const float*)d_in[4];
    const float* W_gnn     = (const float*)d_in[5];
    const float* W_self    = (const float*)d_in[6];
    const float* anchors   = (const float*)d_in[7];
    float* out = (float*)d_out;

    cudaFuncSetAttribute(gemm_kernel<48, DD, DD, 0>,
                         cudaFuncAttributeMaxDynamicSharedMemorySize, GEMM_SMEM);
    cudaFuncSetAttribute(gemm_kernel<32, HH, HH, 1>,
                         cudaFuncAttributeMaxDynamicSharedMemorySize, GEMM_SMEM);

    zero_kernel<<<8, 256>>>();
    anchor_norm_kernel<<<KA, 256>>>(anchors);
    conv_img_concept<<<MTOT, 192>>>(images);
    conv_w_kernel<<<dim3(DD/32, HH/32), 256>>>(W_feat, DD, 0);
    conv_w_kernel<<<dim3(HH/32, HH/32), 256>>>(W_gnn, HH, 1);
    conv_w_kernel<<<dim3(HH/32, HH/32), 256>>>(W_self, HH, 2);

    dim3 gg(MTOT/128, HH/128);
    gemm_kernel<48, DD, DD, 0><<<gg, 256, GEMM_SMEM>>>(b_feat, W_pos, positions);
    agg_kernel<<<MTOT/NPB, 256>>>(positions);
    gemm_kernel<32, HH, HH, 1><<<gg, 256, GEMM_SMEM>>>(nullptr, nullptr, nullptr);
    finalize_kernel<<<(BDIM*(HH+KA) + 255)/256, 256>>>(out);
}

// round 8
// speedup vs baseline: 3.2314x; 1.5840x over previous
#include <cuda_runtime.h>
#include <cuda_fp16.h>
#include <cstdint>
#include <math.h>

#define BDIM 4
#define NN   4096
#define DD   1536
#define HH   512
#define KA   8
#define MTOT (BDIM*NN)
#define R2   (400.0f*400.0f)

// ---------------- static device scratch ----------------------------------
__device__ __align__(16) __half g_img [(size_t)MTOT*DD];
__device__ __align__(16) __half g_feat[(size_t)MTOT*HH];
__device__ __align__(16) __half g_agg [(size_t)MTOT*HH];
__device__ __align__(16) __half g_Wf[HH*DD];   // transposed [H][D]
__device__ __align__(16) __half g_Wg[HH*HH];   // transposed [H][H]
__device__ __align__(16) __half g_Ws[HH*HH];
__device__ __align__(16) float g_anorm_t[DD*KA];   // transposed [D][K]
__device__ float g_concept[BDIM*KA];
__device__ float g_latent[BDIM*HH];

// ---------------- PTX helpers (sm_80-class only) --------------------------
__device__ __forceinline__ uint32_t smem_u32(const void* p) {
    uint32_t a;
    asm("{ .reg .u64 t; cvta.to.shared.u64 t, %1; cvt.u32.u64 %0, t; }" : "=r"(a) : "l"(p));
    return a;
}
__device__ __forceinline__ void cp_async16(uint32_t dst, const void* src) {
    asm volatile("cp.async.cg.shared.global [%0], [%1], 16;\n"
                 :: "r"(dst), "l"(__cvta_generic_to_global(src)) : "memory");
}
__device__ __forceinline__ void ldsm4(uint32_t* r, uint32_t addr) {
    asm volatile("ldmatrix.sync.aligned.m8n8.x4.shared.b16 {%0,%1,%2,%3}, [%4];"
                 : "=r"(r[0]), "=r"(r[1]), "=r"(r[2]), "=r"(r[3]) : "r"(addr));
}
__device__ __forceinline__ void mma16816(float* d, const uint32_t* a, const uint32_t* b) {
    asm volatile("mma.sync.aligned.m16n8k16.row.col.f32.f16.f16.f32 "
                 "{%0,%1,%2,%3}, {%4,%5,%6,%7}, {%8,%9}, {%0,%1,%2,%3};"
                 : "+f"(d[0]), "+f"(d[1]), "+f"(d[2]), "+f"(d[3])
                 : "r"(a[0]), "r"(a[1]), "r"(a[2]), "r"(a[3]), "r"(b[0]), "r"(b[1]));
}
__device__ __forceinline__ uint32_t swz(uint32_t o) { return o ^ ((o >> 3) & 0x70); }

// ---------------- utility kernels ----------------------------------------
__global__ void zero_kernel() {
    int t = blockIdx.x * blockDim.x + threadIdx.x;
    if (t < BDIM*HH) g_latent[t] = 0.0f;
    if (t < BDIM*KA) g_concept[t] = 0.0f;
}

__global__ void anchor_norm_kernel(const float* __restrict__ anchors) {
    int k = blockIdx.x, t = threadIdx.x;
    __shared__ float red[256];
    float s = 0.0f;
    for (int d = t; d < DD; d += 256) { float v = anchors[k*DD + d]; s += v*v; }
    red[t] = s; __syncthreads();
    for (int off = 128; off > 0; off >>= 1) { if (t < off) red[t] += red[t+off]; __syncthreads(); }
    float inv = 1.0f / fmaxf(sqrtf(red[0]), 1e-12f);
    for (int d = t; d < DD; d += 256) g_anorm_t[(size_t)d*KA + k] = anchors[k*DD + d] * inv;
}

// ---- fused: images -> fp16 + cosine concept scores -----------------------
__global__ __launch_bounds__(192) void conv_img_concept(const float* __restrict__ images) {
    int row = blockIdx.x, t = threadIdx.x;
    const float4* x4 = (const float4*)(images + (size_t)row * DD);
    const float4* an4 = (const float4*)g_anorm_t;   // [D][8] -> 2 float4 per d
    float ss = 0.0f;
    float dots[KA];
    #pragma unroll
    for (int k = 0; k < KA; k++) dots[k] = 0.0f;

    #pragma unroll
    for (int half = 0; half < 2; half++) {
        int idx = t + half * 192;       // float4 index within row (0..383)
        float4 v = x4[idx];
        float vv[4] = {v.x, v.y, v.z, v.w};
        #pragma unroll
        for (int e = 0; e < 4; e++) {
            float val = vv[e];
            ss += val * val;
            int d = idx * 4 + e;
            float4 a0 = an4[d*2], a1 = an4[d*2 + 1];
            dots[0] += val*a0.x; dots[1] += val*a0.y; dots[2] += val*a0.z; dots[3] += val*a0.w;
            dots[4] += val*a1.x; dots[5] += val*a1.y; dots[6] += val*a1.z; dots[7] += val*a1.w;
        }
        __half2 p01 = __floats2half2_rn(vv[0], vv[1]);
        __half2 p23 = __floats2half2_rn(vv[2], vv[3]);
        ((uint2*)g_img)[(size_t)row * 384 + idx] =
            make_uint2(*(uint32_t*)&p01, *(uint32_t*)&p23);
    }

    #pragma unroll
    for (int off = 16; off > 0; off >>= 1) {
        ss += __shfl_down_sync(0xffffffffu, ss, off);
        #pragma unroll
        for (int k = 0; k < KA; k++) dots[k] += __shfl_down_sync(0xffffffffu, dots[k], off);
    }
    __shared__ float sred[6][KA + 1];
    int lane = t & 31, wid = t >> 5;
    if (lane == 0) {
        sred[wid][0] = ss;
        #pragma unroll
        for (int k = 0; k < KA; k++) sred[wid][k+1] = dots[k];
    }
    __syncthreads();
    if (t == 0) {
        float S = 0.0f, Dk[KA];
        #pragma unroll
        for (int k = 0; k < KA; k++) Dk[k] = 0.0f;
        #pragma unroll
        for (int w = 0; w < 6; w++) {
            S += sred[w][0];
            #pragma unroll
            for (int k = 0; k < KA; k++) Dk[k] += sred[w][k+1];
        }
        float inv = 1.0f / fmaxf(sqrtf(S), 1e-12f);
        int b = row >> 12;
        #pragma unroll
        for (int k = 0; k < KA; k++)
            atomicAdd(&g_concept[b*KA + k], Dk[k] * inv * (1.0f / NN));
    }
}

// ---- weight transpose via smem tile (coalesced both ways) ---------------
__global__ __launch_bounds__(256) void conv_w_kernel(const float* __restrict__ W, int K, int which) {
    __shared__ float tile[32][33];
    int k0 = blockIdx.x * 32, n0 = blockIdx.y * 32;
    int tx = threadIdx.x & 31, ty = threadIdx.x >> 5;   // 8 rows of 32
    #pragma unroll
    for (int r = 0; r < 32; r += 8)
        tile[ty + r][tx] = W[(size_t)(k0 + ty + r) * HH + n0 + tx];
    __syncthreads();
    #pragma unroll
    for (int r = 0; r < 32; r += 8) {
        int n = n0 + ty + r, k = k0 + tx;
        __half h = __float2half_rn(tile[tx][ty + r]);
        size_t o = (size_t)n * K + k;
        if (which == 0)      g_Wf[o] = h;
        else if (which == 1) g_Wg[o] = h;
        else                 g_Ws[o] = h;
    }
}

// ---------------- HMMA GEMM (fp16, single pass) ---------------------------
// Block tile 128x128, BK=64, 8 warps, warp tile 32x64, 2-stage cp.async.
// MODE 0: feat = img@Wf (+bias+pos@Wp) -> fp16   (24 chunks)
// MODE 1: relu(agg@Wg + feat@Ws) -> column-pool g_latent (16 chunks)
#define STAGE_BYTES 32768
#define SB_OFF 16384
#define COLSUM_OFF 65536
#define GEMM_SMEM  (65536 + 512)

template<int MODE>
__device__ __forceinline__ void get_chunk(int i, const __half*& A, const __half*& B, int& k0) {
    if (MODE == 0) {
        A = g_img; B = g_Wf; k0 = i * 64;
    } else {
        if (i < 8) { A = g_agg;  B = g_Wg; k0 = i * 64; }
        else       { A = g_feat; B = g_Ws; k0 = (i - 8) * 64; }
    }
}

template<int LDA, int LDB, int MODE>
__device__ __forceinline__ void load_chunk(int tid, int m0, int n0, int i, int s, uint32_t sbase) {
    const __half *A, *B; int k0;
    get_chunk<MODE>(i, A, B, k0);
    uint32_t sa = sbase + s * STAGE_BYTES;
    #pragma unroll
    for (int q = 0; q < 4; q++) {
        int e = q * 256 + tid;
        int row = e >> 3, kc = e & 7;
        cp_async16(sa + swz(row * 128 + kc * 16),
                   A + (size_t)(m0 + row) * LDA + k0 + kc * 8);
    }
    #pragma unroll
    for (int q = 0; q < 4; q++) {
        int e = q * 256 + tid;
        int row = e >> 3, kc = e & 7;
        cp_async16(sa + SB_OFF + swz(row * 128 + kc * 16),
                   B + (size_t)(n0 + row) * LDB + k0 + kc * 8);
    }
    asm volatile("cp.async.commit_group;\n" ::: "memory");
}

template<int NCHUNK, int LDA, int LDB, int MODE>
__global__ __launch_bounds__(256, 2) void gemm_kernel(
    const float* __restrict__ bias, const float* __restrict__ Wp,
    const float* __restrict__ pos)
{
    extern __shared__ char smem[];
    uint32_t sbase = smem_u32(smem);
    int tid = threadIdx.x;
    int wid = tid >> 5, lane = tid & 31;
    int m0 = blockIdx.x * 128;
    int n0 = blockIdx.y * 128;

    int warp_m = (wid >> 1) * 32;
    int warp_n = (wid & 1) * 64;

    int a_row  = warp_m + (lane & 15);
    int a_half = (lane >> 4) * 16;
    int b_row  = warp_n + (lane & 7) + ((lane >> 4) * 8);
    int b_half = ((lane >> 3) & 1) * 16;

    float acc[2][8][4];
    #pragma unroll
    for (int mt = 0; mt < 2; mt++)
        #pragma unroll
        for (int nt = 0; nt < 8; nt++)
            #pragma unroll
            for (int j = 0; j < 4; j++) acc[mt][nt][j] = 0.0f;

    if (MODE == 1) {
        for (int c = tid; c < 128; c += 256) *(float*)(smem + COLSUM_OFF + 4*c) = 0.0f;
    }
    __syncthreads();

    load_chunk<LDA,LDB,MODE>(tid, m0, n0, 0, 0, sbase);
    load_chunk<LDA,LDB,MODE>(tid, m0, n0, 1, 1, sbase);

    for (int i = 0; i < NCHUNK; i++) {
        int s = i & 1;
        if (i + 1 < NCHUNK) asm volatile("cp.async.wait_group 1;\n" ::: "memory");
        else                asm volatile("cp.async.wait_group 0;\n" ::: "memory");
        __syncthreads();
        uint32_t sa = sbase + s * STAGE_BYTES;
        #pragma unroll
        for (int ks = 0; ks < 4; ks++) {
            uint32_t afr[2][4], bfr[4][4];
            #pragma unroll
            for (int mt = 0; mt < 2; mt++)
                ldsm4(afr[mt], sa + swz((a_row + mt*16) * 128 + ks*32 + a_half));
            #pragma unroll
            for (int g = 0; g < 4; g++)
                ldsm4(bfr[g], sa + SB_OFF + swz((b_row + g*16) * 128 + ks*32 + b_half));
            #pragma unroll
            for (int mt = 0; mt < 2; mt++)
                #pragma unroll
                for (int g = 0; g < 4; g++) {
                    mma16816(acc[mt][2*g+0], afr[mt], &bfr[g][0]);
                    mma16816(acc[mt][2*g+1], afr[mt], &bfr[g][2]);
                }
        }
        __syncthreads();
        if (i + 2 < NCHUNK)
            load_chunk<LDA,LDB,MODE>(tid, m0, n0, i + 2, s, sbase);
    }

    int r0 = lane >> 2;
    int cp = (lane & 3) * 2;

    if (MODE == 0) {
        float cb[16], cwx[16], cwy[16];
        #pragma unroll
        for (int nt = 0; nt < 8; nt++) {
            int n = n0 + warp_n + nt*8 + cp;
            cb[2*nt]   = bias[n];   cb[2*nt+1]   = bias[n+1];
            cwx[2*nt]  = Wp[n];     cwx[2*nt+1]  = Wp[n+1];
            cwy[2*nt]  = Wp[HH+n];  cwy[2*nt+1]  = Wp[HH+n+1];
        }
        #pragma unroll
        for (int mt = 0; mt < 2; mt++) {
            #pragma unroll
            for (int half = 0; half < 2; half++) {
                int m = m0 + warp_m + mt*16 + r0 + half*8;
                float2 p = *(const float2*)&pos[(size_t)m * 2];
                #pragma unroll
                for (int nt = 0; nt < 8; nt++) {
                    int n = n0 + warp_n + nt*8 + cp;
                    float v0 = acc[mt][nt][2*half+0] + cb[2*nt]   + p.x*cwx[2*nt]   + p.y*cwy[2*nt];
                    float v1 = acc[mt][nt][2*half+1] + cb[2*nt+1] + p.x*cwx[2*nt+1] + p.y*cwy[2*nt+1];
                    __half2 hp = __floats2half2_rn(v0, v1);
                    *(uint32_t*)&g_feat[(size_t)m * HH + n] = *(uint32_t*)&hp;
                }
            }
        }
    } else {
        float* colsum = (float*)(smem + COLSUM_OFF);
        #pragma unroll
        for (int nt = 0; nt < 8; nt++) {
            float s0 = 0.0f, s1 = 0.0f;
            #pragma unroll
            for (int mt = 0; mt < 2; mt++) {
                s0 += fmaxf(acc[mt][nt][0], 0.0f) + fmaxf(acc[mt][nt][2], 0.0f);
                s1 += fmaxf(acc[mt][nt][1], 0.0f) + fmaxf(acc[mt][nt][3], 0.0f);
            }
            #pragma unroll
            for (int off = 4; off <= 16; off <<= 1) {
                s0 += __shfl_xor_sync(0xffffffffu, s0, off);
                s1 += __shfl_xor_sync(0xffffffffu, s1, off);
            }
            if (lane < 4) {
                int c = warp_n + nt*8 + lane*2;
                atomicAdd(&colsum[c], s0);
                atomicAdd(&colsum[c+1], s1);
            }
        }
        __syncthreads();
        int b = m0 >> 12;
        if (tid < 128) atomicAdd(&g_latent[b * HH + n0 + tid], colsum[tid]);
    }
}

// ---------------- radius graph + mean aggregation -------------------------
#define NPB 8
__global__ __launch_bounds__(256) void agg_kernel(const float* __restrict__ pos) {
    int base = blockIdx.x * NPB;
    int b = base >> 12;
    int t = threadIdx.x;
    __shared__ int nlist[NPB][512];
    __shared__ int ncnt[NPB];
    if (t < NPB) ncnt[t] = 0;
    __syncthreads();

    float2 pi[NPB];
    #pragma unroll
    for (int u = 0; u < NPB; u++) pi[u] = *(const float2*)&pos[(size_t)(base + u) * 2];

    for (int j = t; j < NN; j += 256) {
        float2 pj = *(const float2*)&pos[(size_t)(b * NN + j) * 2];
        #pragma unroll
        for (int u = 0; u < NPB; u++) {
            float dx = pi[u].x - pj.x, dy = pi[u].y - pj.y;
            float d2 = dx*dx + dy*dy;
            if (d2 < R2 && (b * NN + j) != (base + u)) {
                int idx = atomicAdd(&ncnt[u], 1);
                if (idx < 512) nlist[u][idx] = j;
            }
        }
    }
    __syncthreads();

    const uint32_t* fh = (const uint32_t*)g_feat + (size_t)b * NN * (HH/2);
    #pragma unroll 1
    for (int u = 0; u < NPB; u++) {
        int cnt = min(ncnt[u], 512);
        float2 acc = make_float2(0.0f, 0.0f);
        for (int l = 0; l < cnt; l++) {
            int j = nlist[u][l];
            uint32_t hv = fh[(size_t)j * (HH/2) + t];
            float2 v = __half22float2(*(__half2*)&hv);
            acc.x += fmaxf(v.x, 0.0f);
            acc.y += fmaxf(v.y, 0.0f);
        }
        float inv = 1.0f / fmaxf((float)cnt, 1.0f);
        __half2 o = __floats2half2_rn(acc.x * inv, acc.y * inv);
        ((uint32_t*)g_agg)[(size_t)(base + u) * (HH/2) + t] = *(uint32_t*)&o;
    }
}

// ---------------- finalize ------------------------------------------------
__global__ void finalize_kernel(float* __restrict__ out) {
    int t = blockIdx.x * blockDim.x + threadIdx.x;
    if (t >= BDIM * (HH + KA)) return;
    int b = t / (HH + KA), c = t % (HH + KA);
    out[t] = (c < HH) ? g_latent[b*HH + c] * (1.0f / NN)
                      : g_concept[b*KA + (c - HH)];
}

// ---------------- launch --------------------------------------------------
extern "C" void kernel_launch(void* const* d_in, const int* in_sizes, int n_in,
                              void* d_out, int out_size)
{
    const float* images    = (const float*)d_in[0];
    const float* positions = (const float*)d_in[1];
    const float* W_feat    = (const float*)d_in[2];
    const float* b_feat    = (const float*)d_in[3];
    const float* W_pos     = (const float*)d_in[4];
    const float* W_gnn     = (const float*)d_in[5];
    const float* W_self    = (const float*)d_in[6];
    const float* anchors   = (const float*)d_in[7];
    float* out = (float*)d_out;

    cudaFuncSetAttribute(gemm_kernel<24, DD, DD, 0>,
                         cudaFuncAttributeMaxDynamicSharedMemorySize, GEMM_SMEM);
    cudaFuncSetAttribute(gemm_kernel<16, HH, HH, 1>,
                         cudaFuncAttributeMaxDynamicSharedMemorySize, GEMM_SMEM);

    dim3 gg(MTOT/128, HH/128);
    // launch order chosen so ncu (-s 5 -c 1) profiles the feat GEMM (index 5)
    zero_kernel<<<8, 256>>>();                                    // 0
    anchor_norm_kernel<<<KA, 256>>>(anchors);                     // 1
    conv_img_concept<<<MTOT, 192>>>(images);                      // 2
    conv_w_kernel<<<dim3(DD/32, HH/32), 256>>>(W_feat, DD, 0);    // 3
    conv_w_kernel<<<dim3(HH/32, HH/32), 256>>>(W_gnn, HH, 1);     // 4
    gemm_kernel<24, DD, DD, 0><<<gg, 256, GEMM_SMEM>>>(b_feat, W_pos, positions);  // 5 <- profiled
    conv_w_kernel<<<dim3(HH/32, HH/32), 256>>>(W_self, HH, 2);    // 6
    agg_kernel<<<MTOT/NPB, 256>>>(positions);                     // 7
    gemm_kernel<16, HH, HH, 1><<<gg, 256, GEMM_SMEM>>>(nullptr, nullptr, nullptr); // 8
    finalize_kernel<<<(BDIM*(HH+KA) + 255)/256, 256>>>(out);      // 9
}